// round 7
// baseline (speedup 1.0000x reference)
#include <cuda_runtime.h>
#include <cuda_bf16.h>
#include <cstdint>
#include <math.h>

// ============================================================
// x(1024,512) f32, prototypes(100,10,512) f32, log_dist_scales(100,10,512) f32
// out(1024,100) = logsumexp_p( -( sum_d w*(x-p)^2 ) ),  w = exp(ls)
// dist[b,cp] = [x^2, x] . [w, -2wp]^T + t3[cp]
// R7: R2's verified GEMM (BM128/BN64, warp 32x32, ~4.4 cyc/HMMA = mma.sync
// roofline) + fast cp.async-pipelined LSE + vectorized prep.
// ============================================================

#define MB 1024
#define ND 1024
#define KD 1024

#define BM 128
#define BN 64
#define BK 64
#define NKT (KD / BK)   // 16

// ---------------- device scratch ----------------
__device__ __nv_bfloat16 g_A[MB * KD];    // [b][k]  k<512: x^2, k>=512: x
__device__ __nv_bfloat16 g_Bm[ND * KD];   // [cp][k] k<512: w, k>=512: -2wp (rows>=1000 zero)
__device__ float g_t3[1000];
__device__ float g_dist[MB * ND];

// ---------------- helpers ----------------
__device__ __forceinline__ uint32_t smem_u32(const void* p) {
    uint32_t a;
    asm("{ .reg .u64 t; cvta.to.shared.u64 t, %1; cvt.u32.u64 %0, t; }" : "=r"(a) : "l"(p));
    return a;
}
__device__ __forceinline__ uint32_t sw128(uint32_t off) {
    return off ^ ((off >> 3) & 0x70);
}
#define CP_ASYNC16(dst, src) \
    asm volatile("cp.async.cg.shared.global [%0], [%1], 16;" :: "r"(dst), "l"(src) : "memory")
#define CP_COMMIT() asm volatile("cp.async.commit_group;" ::: "memory")
#define CP_WAIT1()  asm volatile("cp.async.wait_group 1;" ::: "memory")
#define CP_WAIT0()  asm volatile("cp.async.wait_group 0;" ::: "memory")

#define LDMATRIX_X4(r0, r1, r2, r3, addr) \
    asm volatile("ldmatrix.sync.aligned.m8n8.x4.shared.b16 {%0,%1,%2,%3}, [%4];" \
                 : "=r"(r0), "=r"(r1), "=r"(r2), "=r"(r3) : "r"(addr))
#define LDMATRIX_X2(r0, r1, addr) \
    asm volatile("ldmatrix.sync.aligned.m8n8.x2.shared.b16 {%0,%1}, [%2];" \
                 : "=r"(r0), "=r"(r1) : "r"(addr))
#define MMA_16816(c0, c1, c2, c3, a0, a1, a2, a3, b0, b1) \
    asm volatile("mma.sync.aligned.m16n8k16.row.col.f32.bf16.bf16.f32 " \
                 "{%0,%1,%2,%3}, {%4,%5,%6,%7}, {%8,%9}, {%0,%1,%2,%3};" \
                 : "+f"(c0), "+f"(c1), "+f"(c2), "+f"(c3) \
                 : "r"(a0), "r"(a1), "r"(a2), "r"(a3), "r"(b0), "r"(b1))

// ---------------- vectorized prep ----------------
// blocks [0,512): x -> g_A (float4/thread); blocks [512,1512): proto -> g_Bm + t3
__global__ void prep_kernel(const float* __restrict__ x,
                            const float* __restrict__ proto,
                            const float* __restrict__ ls) {
    if (blockIdx.x < 512) {
        int idx = blockIdx.x * 256 + threadIdx.x;   // float4 index
        int b  = idx >> 7;
        int d0 = (idx & 127) * 4;
        float4 v = reinterpret_cast<const float4*>(x)[idx];
        __nv_bfloat162* a0 = reinterpret_cast<__nv_bfloat162*>(g_A + b * KD + d0);
        __nv_bfloat162* a1 = reinterpret_cast<__nv_bfloat162*>(g_A + b * KD + 512 + d0);
        a0[0] = __floats2bfloat162_rn(v.x * v.x, v.y * v.y);
        a0[1] = __floats2bfloat162_rn(v.z * v.z, v.w * v.w);
        a1[0] = __floats2bfloat162_rn(v.x, v.y);
        a1[1] = __floats2bfloat162_rn(v.z, v.w);
    } else {
        int cp  = blockIdx.x - 512;   // 0..999
        int tid = threadIdx.x;        // 256, each a float2
        int d0  = tid * 2;
        float2 lw = *reinterpret_cast<const float2*>(ls + cp * 512 + d0);
        float2 pp = *reinterpret_cast<const float2*>(proto + cp * 512 + d0);
        float w0 = expf(lw.x), w1 = expf(lw.y);
        *reinterpret_cast<__nv_bfloat162*>(g_Bm + cp * KD + d0) =
            __floats2bfloat162_rn(w0, w1);
        *reinterpret_cast<__nv_bfloat162*>(g_Bm + cp * KD + 512 + d0) =
            __floats2bfloat162_rn(-2.0f * w0 * pp.x, -2.0f * w1 * pp.y);
        float acc = w0 * pp.x * pp.x + w1 * pp.y * pp.y;
        #pragma unroll
        for (int o = 16; o > 0; o >>= 1) acc += __shfl_xor_sync(0xffffffffu, acc, o);
        __shared__ float red[8];
        if ((tid & 31) == 0) red[tid >> 5] = acc;
        __syncthreads();
        if (tid == 0) {
            float s = 0.f;
            #pragma unroll
            for (int i = 0; i < 8; i++) s += red[i];
            g_t3[cp] = s;
        }
    }
}

// ---------------- GEMM (R2 verbatim): mma.sync bf16, 128x64 tiles, 2-stage cp.async ----------------
#define SA_OFF(buf) ((buf) * 16384)
#define SB_OFF(buf) (32768 + (buf) * 8192)

__global__ __launch_bounds__(256, 1) void gemm_kernel() {
    __shared__ __align__(1024) char smem[49152];
    const uint32_t sbase = smem_u32(smem);
    const int tid = threadIdx.x;
    const int wid = tid >> 5;
    const int lid = tid & 31;
    const int m0 = blockIdx.y * BM;
    const int n0 = blockIdx.x * BN;

    const __nv_bfloat16* a_src[4];
    uint32_t a_dst[4];
    #pragma unroll
    for (int i = 0; i < 4; i++) {
        int q = tid + i * 256;
        int r = q >> 3, c = q & 7;
        a_src[i] = g_A + (size_t)(m0 + r) * KD + c * 8;
        a_dst[i] = sw128((uint32_t)r * 128u + (uint32_t)c * 16u);
    }
    const __nv_bfloat16* b_src[2];
    uint32_t b_dst[2];
    #pragma unroll
    for (int i = 0; i < 2; i++) {
        int q = tid + i * 256;
        int r = q >> 3, c = q & 7;
        b_src[i] = g_Bm + (size_t)(n0 + r) * KD + c * 8;
        b_dst[i] = sw128((uint32_t)r * 128u + (uint32_t)c * 16u);
    }

    // warp layout: 4 (M) x 2 (N); warp tile 32x32
    const int wm = (wid >> 1) * 32;
    const int wn = (wid & 1) * 32;

    float acc[2][4][4];
    #pragma unroll
    for (int mf = 0; mf < 2; mf++)
        #pragma unroll
        for (int nf = 0; nf < 4; nf++)
            #pragma unroll
            for (int i = 0; i < 4; i++) acc[mf][nf][i] = 0.f;

    const int l4 = lid & 15;
    uint32_t a_lm_off[2][4];
    uint32_t b_lm_off[4][4];
    #pragma unroll
    for (int mf = 0; mf < 2; mf++)
        #pragma unroll
        for (int ks = 0; ks < 4; ks++) {
            uint32_t r = wm + mf * 16 + (lid & 15);
            uint32_t ch = ks * 2 + (lid >> 4);
            a_lm_off[mf][ks] = sw128(r * 128u + ch * 16u);
        }
    #pragma unroll
    for (int nf = 0; nf < 4; nf++)
        #pragma unroll
        for (int ks = 0; ks < 4; ks++) {
            uint32_t r = wn + nf * 8 + (l4 & 7);
            uint32_t ch = ks * 2 + (l4 >> 3);
            b_lm_off[nf][ks] = sw128(r * 128u + ch * 16u);
        }

    {
        uint32_t sa = sbase + SA_OFF(0), sb = sbase + SB_OFF(0);
        #pragma unroll
        for (int i = 0; i < 4; i++) CP_ASYNC16(sa + a_dst[i], a_src[i]);
        #pragma unroll
        for (int i = 0; i < 2; i++) CP_ASYNC16(sb + b_dst[i], b_src[i]);
        CP_COMMIT();
    }

    for (int kt = 0; kt < NKT; kt++) {
        if (kt + 1 < NKT) {
            int nb = (kt + 1) & 1;
            uint32_t sa = sbase + SA_OFF(nb), sb = sbase + SB_OFF(nb);
            #pragma unroll
            for (int i = 0; i < 4; i++) CP_ASYNC16(sa + a_dst[i], a_src[i] + (kt + 1) * BK);
            #pragma unroll
            for (int i = 0; i < 2; i++) CP_ASYNC16(sb + b_dst[i], b_src[i] + (kt + 1) * BK);
            CP_COMMIT();
            CP_WAIT1();
        } else {
            CP_WAIT0();
        }
        __syncthreads();

        const uint32_t sa = sbase + SA_OFF(kt & 1);
        const uint32_t sb = sbase + SB_OFF(kt & 1);
        #pragma unroll
        for (int ks = 0; ks < 4; ks++) {
            uint32_t a[2][4], b[4][2];
            #pragma unroll
            for (int mf = 0; mf < 2; mf++)
                LDMATRIX_X4(a[mf][0], a[mf][1], a[mf][2], a[mf][3], sa + a_lm_off[mf][ks]);
            #pragma unroll
            for (int nf = 0; nf < 4; nf++)
                LDMATRIX_X2(b[nf][0], b[nf][1], sb + b_lm_off[nf][ks]);
            #pragma unroll
            for (int mf = 0; mf < 2; mf++)
                #pragma unroll
                for (int nf = 0; nf < 4; nf++)
                    MMA_16816(acc[mf][nf][0], acc[mf][nf][1], acc[mf][nf][2], acc[mf][nf][3],
                              a[mf][0], a[mf][1], a[mf][2], a[mf][3], b[nf][0], b[nf][1]);
        }
        __syncthreads();
    }

    const int qr = lid >> 2;
    const int qc = (lid & 3) * 2;
    #pragma unroll
    for (int mf = 0; mf < 2; mf++) {
        #pragma unroll
        for (int nf = 0; nf < 4; nf++) {
            int row = m0 + wm + mf * 16 + qr;
            int col = n0 + wn + nf * 8 + qc;
            *reinterpret_cast<float2*>(g_dist + (size_t)row * ND + col) =
                make_float2(acc[mf][nf][0], acc[mf][nf][1]);
            *reinterpret_cast<float2*>(g_dist + (size_t)(row + 8) * ND + col) =
                make_float2(acc[mf][nf][2], acc[mf][nf][3]);
        }
    }
}

// ---------------- fast LSE: cp.async double-buffered row staging ----------------
// 128 blocks x 8 rows; coalesced float4 loads; coalesced out writes.
__global__ __launch_bounds__(256) void lse_kernel(float* __restrict__ out) {
    __shared__ float st3[1000];
    __shared__ __align__(16) float rowbuf[2][1000];
    const int tid = threadIdx.x;
    const int b0 = blockIdx.x * 8;

    for (int i = tid; i < 1000; i += 256) st3[i] = g_t3[i];

    if (tid < 250)
        CP_ASYNC16(smem_u32(&rowbuf[0][tid * 4]), g_dist + (size_t)b0 * ND + tid * 4);
    CP_COMMIT();

    for (int r = 0; r < 8; r++) {
        if (r < 7) {
            if (tid < 250)
                CP_ASYNC16(smem_u32(&rowbuf[(r + 1) & 1][tid * 4]),
                           g_dist + (size_t)(b0 + r + 1) * ND + tid * 4);
            CP_COMMIT();
            CP_WAIT1();
        } else {
            CP_WAIT0();
        }
        __syncthreads();

        if (tid < 100) {
            const float* sp = &rowbuf[r & 1][tid * 10];
            const float* tp = &st3[tid * 10];
            float v[10], mx = -3.4e38f;
            #pragma unroll
            for (int p = 0; p < 10; p++) {
                v[p] = -(sp[p] + tp[p]);
                mx = fmaxf(mx, v[p]);
            }
            float s = 0.f;
            #pragma unroll
            for (int p = 0; p < 10; p++) s += expf(v[p] - mx);
            out[(size_t)(b0 + r) * 100 + tid] = mx + logf(s);
        }
        __syncthreads();
    }
}

// ---------------- launch ----------------
extern "C" void kernel_launch(void* const* d_in, const int* in_sizes, int n_in,
                              void* d_out, int out_size) {
    const float* x     = (const float*)d_in[0];  // (1024, 512)
    const float* proto = (const float*)d_in[1];  // (100, 10, 512)
    const float* ls    = (const float*)d_in[2];  // (100, 10, 512)
    float* out = (float*)d_out;                  // (1024, 100)

    prep_kernel<<<1512, 256>>>(x, proto, ls);
    gemm_kernel<<<dim3(ND / BN, MB / BM), 256>>>();
    lse_kernel<<<128, 256>>>(out);
}

// round 8
// speedup vs baseline: 1.3283x; 1.3283x over previous
#include <cuda_runtime.h>
#include <cuda_bf16.h>
#include <cstdint>
#include <math.h>

// ============================================================
// x(1024,512) f32, prototypes(100,10,512) f32, log_dist_scales(100,10,512) f32
// out(1024,100) = logsumexp_p( -( sum_d w*(x-p)^2 ) ),  w = exp(ls)
// dist = t1 + (-2*t2 + t3);  t1 = sum w x^2, t2 = sum (wp)x, t3 = sum w p^2
// R8: mma.sync rate is a hard floor (~6.2cyc/HMMA/SM, R4-R7 evidence), so
// shrink the GEMM: when w==1 (ls all zero), t1 = |x|^2 is rank-1 and slides
// out of the LSE -> K halves to 512. Runtime-detected (flag), general.
// Slow path = R4's proven full-K code.
// ============================================================

#define MB 1024
#define KD 1024

#define BM 256
#define BN 40
#define BK 64
#define NKT (KD / BK)   // 16

// ---------------- device scratch ----------------
__device__ __nv_bfloat16 g_A[MB * KD];     // [b][k]  k<512: x^2, k>=512: x
__device__ __nv_bfloat16 g_Bm[1000 * KD];  // [cp][k] k<512: w,   k>=512: -2wp
__device__ float g_t3[1000];               // sum w p^2
__device__ float g_t1[MB];                 // sum x^2 (fp32 exact)
__device__ int   g_flag;                   // 1 if any ls != 0

// ---------------- helpers ----------------
__device__ __forceinline__ uint32_t smem_u32(const void* p) {
    uint32_t a;
    asm("{ .reg .u64 t; cvta.to.shared.u64 t, %1; cvt.u32.u64 %0, t; }" : "=r"(a) : "l"(p));
    return a;
}
__device__ __forceinline__ uint32_t sw128(uint32_t off) {
    return off ^ ((off >> 3) & 0x70);
}
#define CP_ASYNC16(dst, src) \
    asm volatile("cp.async.cg.shared.global [%0], [%1], 16;" :: "r"(dst), "l"(src) : "memory")
#define CP_COMMIT() asm volatile("cp.async.commit_group;" ::: "memory")
#define CP_WAIT1()  asm volatile("cp.async.wait_group 1;" ::: "memory")
#define CP_WAIT0()  asm volatile("cp.async.wait_group 0;" ::: "memory")

#define LDMATRIX_X4(r0, r1, r2, r3, addr) \
    asm volatile("ldmatrix.sync.aligned.m8n8.x4.shared.b16 {%0,%1,%2,%3}, [%4];" \
                 : "=r"(r0), "=r"(r1), "=r"(r2), "=r"(r3) : "r"(addr))
#define LDMATRIX_X2(r0, r1, addr) \
    asm volatile("ldmatrix.sync.aligned.m8n8.x2.shared.b16 {%0,%1}, [%2];" \
                 : "=r"(r0), "=r"(r1) : "r"(addr))
#define MMA_16816(c0, c1, c2, c3, a0, a1, a2, a3, b0, b1) \
    asm volatile("mma.sync.aligned.m16n8k16.row.col.f32.bf16.bf16.f32 " \
                 "{%0,%1,%2,%3}, {%4,%5,%6,%7}, {%8,%9}, {%0,%1,%2,%3};" \
                 : "+f"(c0), "+f"(c1), "+f"(c2), "+f"(c3) \
                 : "r"(a0), "r"(a1), "r"(a2), "r"(a3), "r"(b0), "r"(b1))

// ---------------- kernel 0: flag reset + exact fp32 t1 row sums ----------------
// 128 blocks x 8 warps; warp w handles row b = blockIdx*8 + w.
__global__ void t1_kernel(const float* __restrict__ x) {
    if (blockIdx.x == 0 && threadIdx.x == 0) g_flag = 0;
    int wid = threadIdx.x >> 5;
    int lid = threadIdx.x & 31;
    int b = blockIdx.x * 8 + wid;
    const float4* row = reinterpret_cast<const float4*>(x + (size_t)b * 512);
    float s = 0.f;
    #pragma unroll
    for (int j = 0; j < 4; j++) {
        float4 v = row[lid + 32 * j];
        s += v.x * v.x + v.y * v.y + v.z * v.z + v.w * v.w;
    }
    #pragma unroll
    for (int o = 16; o > 0; o >>= 1) s += __shfl_xor_sync(0xffffffffu, s, o);
    if (lid == 0) g_t1[b] = s;
}

// ---------------- vectorized prep (R6) + flag detection ----------------
__global__ void prep_kernel(const float* __restrict__ x,
                            const float* __restrict__ proto,
                            const float* __restrict__ ls) {
    if (blockIdx.x < 512) {
        int idx = blockIdx.x * 256 + threadIdx.x;   // float4 index
        int b  = idx >> 7;
        int d0 = (idx & 127) * 4;
        float4 v = reinterpret_cast<const float4*>(x)[idx];
        __nv_bfloat162* a0 = reinterpret_cast<__nv_bfloat162*>(g_A + b * KD + d0);
        __nv_bfloat162* a1 = reinterpret_cast<__nv_bfloat162*>(g_A + b * KD + 512 + d0);
        a0[0] = __floats2bfloat162_rn(v.x * v.x, v.y * v.y);
        a0[1] = __floats2bfloat162_rn(v.z * v.z, v.w * v.w);
        a1[0] = __floats2bfloat162_rn(v.x, v.y);
        a1[1] = __floats2bfloat162_rn(v.z, v.w);
    } else {
        int cp  = blockIdx.x - 512;   // 0..999
        int tid = threadIdx.x;        // 256, each a float2
        int d0  = tid * 2;
        float2 lw = *reinterpret_cast<const float2*>(ls + cp * 512 + d0);
        float2 pp = *reinterpret_cast<const float2*>(proto + cp * 512 + d0);
        // flag: any nonzero log scale anywhere -> slow (general) path
        unsigned nz = __ballot_sync(0xffffffffu, lw.x != 0.f || lw.y != 0.f);
        if (nz && (tid & 31) == 0) atomicOr(&g_flag, 1);
        float w0 = expf(lw.x), w1 = expf(lw.y);
        *reinterpret_cast<__nv_bfloat162*>(g_Bm + cp * KD + d0) =
            __floats2bfloat162_rn(w0, w1);
        *reinterpret_cast<__nv_bfloat162*>(g_Bm + cp * KD + 512 + d0) =
            __floats2bfloat162_rn(-2.0f * w0 * pp.x, -2.0f * w1 * pp.y);
        float acc = w0 * pp.x * pp.x + w1 * pp.y * pp.y;
        #pragma unroll
        for (int o = 16; o > 0; o >>= 1) acc += __shfl_xor_sync(0xffffffffu, acc, o);
        __shared__ float red[8];
        if ((tid & 31) == 0) red[tid >> 5] = acc;
        __syncthreads();
        if (tid == 0) {
            float s = 0.f;
            #pragma unroll
            for (int i = 0; i < 8; i++) s += red[i];
            g_t3[cp] = s;
        }
    }
}

// ---------------- GEMM + fused LSE (R4 base, runtime kstart) ----------------
// SMEM: A[2][256][64] bf16 (SW128, 32KB each), B[2][40][64] bf16 (5KB each)
#define SA_OFF(buf) ((buf) * 32768)
#define SB_OFF(buf) (65536 + (buf) * 5120)
#define SMEM_TOTAL  (65536 + 2 * 5120)      // 75776
#define SST_STRIDE  44
#define T3_OFF      (256 * SST_STRIDE * 4)  // 45056

__global__ __launch_bounds__(256, 1) void gemm_lse_kernel(float* __restrict__ out) {
    extern __shared__ char smem[];
    const uint32_t sbase = smem_u32(smem);
    const int tid = threadIdx.x;
    const int wid = tid >> 5;
    const int lid = tid & 31;
    const int m0 = blockIdx.y * BM;
    const int n0 = blockIdx.x * BN;

    const int flag = g_flag;
    const int kstart = flag ? 0 : 8;   // fast path: only the x-part (k 512..1023)

    // ---- load plan: A 2048 chunks (8/thread); B 320 chunks (2/thread, guarded)
    const __nv_bfloat16* a_src[8];
    uint32_t a_dst[8];
    #pragma unroll
    for (int i = 0; i < 8; i++) {
        int q = tid + i * 256;
        int r = q >> 3, c = q & 7;
        a_src[i] = g_A + (size_t)(m0 + r) * KD + c * 8;
        a_dst[i] = sw128((uint32_t)r * 128u + (uint32_t)c * 16u);
    }
    const __nv_bfloat16* b_src[2];
    uint32_t b_dst[2];
    bool b_ok[2];
    #pragma unroll
    for (int i = 0; i < 2; i++) {
        int q = tid + i * 256;
        int r = q >> 3, c = q & 7;
        b_ok[i] = (q < 320);
        b_src[i] = g_Bm + (size_t)(n0 + (b_ok[i] ? r : 0)) * KD + c * 8;
        b_dst[i] = sw128((uint32_t)(b_ok[i] ? r : 0) * 128u + (uint32_t)c * 16u);
    }

    // warp layout: 8 warps in M; warp tile 32 x 40
    const int wm = wid * 32;

    float acc[2][5][4];
    #pragma unroll
    for (int mf = 0; mf < 2; mf++)
        #pragma unroll
        for (int nf = 0; nf < 5; nf++)
            #pragma unroll
            for (int i = 0; i < 4; i++) acc[mf][nf][i] = 0.f;

    const int l4 = lid & 15;
    uint32_t a_lm_off[2][4];
    uint32_t b_lm_off[5][4];
    #pragma unroll
    for (int mf = 0; mf < 2; mf++)
        #pragma unroll
        for (int ks = 0; ks < 4; ks++) {
            uint32_t r = wm + mf * 16 + (lid & 15);
            uint32_t ch = ks * 2 + (lid >> 4);
            a_lm_off[mf][ks] = sw128(r * 128u + ch * 16u);
        }
    #pragma unroll
    for (int nf = 0; nf < 5; nf++)
        #pragma unroll
        for (int ks = 0; ks < 4; ks++) {
            uint32_t r = nf * 8 + (l4 & 7);
            uint32_t ch = ks * 2 + (l4 >> 3);
            b_lm_off[nf][ks] = sw128(r * 128u + ch * 16u);
        }

    // ---- prologue: tile kstart ----
    {
        int buf = kstart & 1;
        uint32_t sa = sbase + SA_OFF(buf), sb = sbase + SB_OFF(buf);
        #pragma unroll
        for (int i = 0; i < 8; i++) CP_ASYNC16(sa + a_dst[i], a_src[i] + kstart * BK);
        #pragma unroll
        for (int i = 0; i < 2; i++) if (b_ok[i]) CP_ASYNC16(sb + b_dst[i], b_src[i] + kstart * BK);
        CP_COMMIT();
    }

    for (int kt = kstart; kt < NKT; kt++) {
        if (kt + 1 < NKT) {
            int nb = (kt + 1) & 1;
            uint32_t sa = sbase + SA_OFF(nb), sb = sbase + SB_OFF(nb);
            #pragma unroll
            for (int i = 0; i < 8; i++) CP_ASYNC16(sa + a_dst[i], a_src[i] + (kt + 1) * BK);
            #pragma unroll
            for (int i = 0; i < 2; i++) if (b_ok[i]) CP_ASYNC16(sb + b_dst[i], b_src[i] + (kt + 1) * BK);
            CP_COMMIT();
            CP_WAIT1();
        } else {
            CP_WAIT0();
        }
        __syncthreads();

        const uint32_t sa = sbase + SA_OFF(kt & 1);
        const uint32_t sb = sbase + SB_OFF(kt & 1);
        #pragma unroll
        for (int ks = 0; ks < 4; ks++) {
            uint32_t a[2][4], b[5][2];
            #pragma unroll
            for (int mf = 0; mf < 2; mf++)
                LDMATRIX_X4(a[mf][0], a[mf][1], a[mf][2], a[mf][3], sa + a_lm_off[mf][ks]);
            #pragma unroll
            for (int nf = 0; nf < 5; nf++)
                LDMATRIX_X2(b[nf][0], b[nf][1], sb + b_lm_off[nf][ks]);
            #pragma unroll
            for (int mf = 0; mf < 2; mf++)
                #pragma unroll
                for (int nf = 0; nf < 5; nf++)
                    MMA_16816(acc[mf][nf][0], acc[mf][nf][1], acc[mf][nf][2], acc[mf][nf][3],
                              a[mf][0], a[mf][1], a[mf][2], a[mf][3], b[nf][0], b[nf][1]);
        }
        __syncthreads();
    }

    // ---- fused epilogue: fragments -> SMEM stage -> per-(row,class) logsumexp ----
    float* sst = reinterpret_cast<float*>(smem);            // [256][44]
    float* st3 = reinterpret_cast<float*>(smem + T3_OFF);   // [40]
    if (tid < 40) st3[tid] = g_t3[n0 + tid];

    const int qr = lid >> 2;
    const int qc = (lid & 3) * 2;
    #pragma unroll
    for (int mf = 0; mf < 2; mf++) {
        int row = wm + mf * 16 + qr;
        #pragma unroll
        for (int nf = 0; nf < 5; nf++) {
            int col = nf * 8 + qc;
            *reinterpret_cast<float2*>(&sst[row * SST_STRIDE + col]) =
                make_float2(acc[mf][nf][0], acc[mf][nf][1]);
            *reinterpret_cast<float2*>(&sst[(row + 8) * SST_STRIDE + col]) =
                make_float2(acc[mf][nf][2], acc[mf][nf][3]);
        }
    }
    __syncthreads();

    // 256 rows x 4 classes = 1024 tasks, 4 per thread
    const int c0 = blockIdx.x * 4;
    #pragma unroll
    for (int i = 0; i < 4; i++) {
        int task = tid + i * 256;
        int row = task >> 2;
        int cls = task & 3;
        const float* sp = &sst[row * SST_STRIDE + cls * 10];
        const float* tp = &st3[cls * 10];
        float v[10], mx = -3.4e38f;
        #pragma unroll
        for (int p = 0; p < 10; p++) {
            v[p] = -(sp[p] + tp[p]);
            mx = fmaxf(mx, v[p]);
        }
        float s = 0.f;
        #pragma unroll
        for (int p = 0; p < 10; p++) s += expf(v[p] - mx);
        float t1v = flag ? 0.f : g_t1[m0 + row];   // fast path: t1 slid out of lse
        out[(size_t)(m0 + row) * 100 + c0 + cls] = mx + logf(s) - t1v;
    }
}

// ---------------- launch ----------------
extern "C" void kernel_launch(void* const* d_in, const int* in_sizes, int n_in,
                              void* d_out, int out_size) {
    const float* x     = (const float*)d_in[0];  // (1024, 512)
    const float* proto = (const float*)d_in[1];  // (100, 10, 512)
    const float* ls    = (const float*)d_in[2];  // (100, 10, 512)
    float* out = (float*)d_out;                  // (1024, 100)

    cudaFuncSetAttribute(gemm_lse_kernel, cudaFuncAttributeMaxDynamicSharedMemorySize, SMEM_TOTAL);

    t1_kernel<<<128, 256>>>(x);                  // resets g_flag, computes t1 (fp32)
    prep_kernel<<<1512, 256>>>(x, proto, ls);    // sets g_flag if any ls != 0
    gemm_lse_kernel<<<dim3(25, MB / BM), 256, SMEM_TOTAL>>>(out);
}

// round 9
// speedup vs baseline: 1.5193x; 1.1438x over previous
#include <cuda_runtime.h>
#include <cuda_bf16.h>
#include <cstdint>
#include <math.h>

// ============================================================
// x(1024,512) f32, prototypes(100,10,512) f32, log_dist_scales(100,10,512) f32
// out(1024,100) = logsumexp_p( -( sum_d w*(x-p)^2 ) ),  w = exp(ls)
// dist = t1 + (-2*t2 + t3);  t1 = sum w x^2, t2 = sum (wp)x, t3 = sum w p^2
// R9: t1_kernel folded into prep (saves 4.3us launch); prep widened to
// 16B/8B stores with 8/4 elems per thread; sticky g_flag (no reset kernel).
// Fast path (ls==0): K=512 GEMM + t1 slid out of the LSE. Slow path = full K.
// ============================================================

#define MB 1024
#define KD 1024

#define BM 256
#define BN 40
#define BK 64
#define NKT (KD / BK)   // 16

// ---------------- device scratch ----------------
__device__ __nv_bfloat16 g_A[MB * KD];     // [b][k]  k<512: x^2, k>=512: x
__device__ __nv_bfloat16 g_Bm[1000 * KD];  // [cp][k] k<512: w,   k>=512: -2wp
__device__ float g_t3[1000];               // sum w p^2
__device__ float g_t1[MB];                 // sum x^2 (fp32 exact)
__device__ int   g_flag;                   // sticky: 1 if any ls != 0 (zero-init)

// ---------------- helpers ----------------
__device__ __forceinline__ uint32_t smem_u32(const void* p) {
    uint32_t a;
    asm("{ .reg .u64 t; cvta.to.shared.u64 t, %1; cvt.u32.u64 %0, t; }" : "=r"(a) : "l"(p));
    return a;
}
__device__ __forceinline__ uint32_t sw128(uint32_t off) {
    return off ^ ((off >> 3) & 0x70);
}
#define CP_ASYNC16(dst, src) \
    asm volatile("cp.async.cg.shared.global [%0], [%1], 16;" :: "r"(dst), "l"(src) : "memory")
#define CP_COMMIT() asm volatile("cp.async.commit_group;" ::: "memory")
#define CP_WAIT1()  asm volatile("cp.async.wait_group 1;" ::: "memory")
#define CP_WAIT0()  asm volatile("cp.async.wait_group 0;" ::: "memory")

#define LDMATRIX_X4(r0, r1, r2, r3, addr) \
    asm volatile("ldmatrix.sync.aligned.m8n8.x4.shared.b16 {%0,%1,%2,%3}, [%4];" \
                 : "=r"(r0), "=r"(r1), "=r"(r2), "=r"(r3) : "r"(addr))
#define LDMATRIX_X2(r0, r1, addr) \
    asm volatile("ldmatrix.sync.aligned.m8n8.x2.shared.b16 {%0,%1}, [%2];" \
                 : "=r"(r0), "=r"(r1) : "r"(addr))
#define MMA_16816(c0, c1, c2, c3, a0, a1, a2, a3, b0, b1) \
    asm volatile("mma.sync.aligned.m16n8k16.row.col.f32.bf16.bf16.f32 " \
                 "{%0,%1,%2,%3}, {%4,%5,%6,%7}, {%8,%9}, {%0,%1,%2,%3};" \
                 : "+f"(c0), "+f"(c1), "+f"(c2), "+f"(c3) \
                 : "r"(a0), "r"(a1), "r"(a2), "r"(a3), "r"(b0), "r"(b1))

// ---------------- prep: x + t1 (blocks 0..255), proto + t3 + flag (blocks 256..755)
__global__ void prep_kernel(const float* __restrict__ x,
                            const float* __restrict__ proto,
                            const float* __restrict__ ls) {
    const int tid = threadIdx.x;
    if (blockIdx.x < 256) {
        // 8 x-elements per thread; 64 threads (2 warps) per row; 4 rows per block
        int idx = blockIdx.x * 256 + tid;
        int b  = idx >> 6;
        int d0 = (idx & 63) * 8;
        const float4* src = reinterpret_cast<const float4*>(x) + idx * 2;
        float4 v0 = src[0], v1 = src[1];
        __nv_bfloat162 hs[4], hx[4];
        hs[0] = __floats2bfloat162_rn(v0.x * v0.x, v0.y * v0.y);
        hs[1] = __floats2bfloat162_rn(v0.z * v0.z, v0.w * v0.w);
        hs[2] = __floats2bfloat162_rn(v1.x * v1.x, v1.y * v1.y);
        hs[3] = __floats2bfloat162_rn(v1.z * v1.z, v1.w * v1.w);
        hx[0] = __floats2bfloat162_rn(v0.x, v0.y);
        hx[1] = __floats2bfloat162_rn(v0.z, v0.w);
        hx[2] = __floats2bfloat162_rn(v1.x, v1.y);
        hx[3] = __floats2bfloat162_rn(v1.z, v1.w);
        *reinterpret_cast<uint4*>(g_A + (size_t)b * KD + d0)       = *reinterpret_cast<uint4*>(hs);
        *reinterpret_cast<uint4*>(g_A + (size_t)b * KD + 512 + d0) = *reinterpret_cast<uint4*>(hx);
        // exact fp32 t1 row sums (row = 2 warps)
        float s = v0.x * v0.x + v0.y * v0.y + v0.z * v0.z + v0.w * v0.w
                + v1.x * v1.x + v1.y * v1.y + v1.z * v1.z + v1.w * v1.w;
        #pragma unroll
        for (int o = 16; o > 0; o >>= 1) s += __shfl_xor_sync(0xffffffffu, s, o);
        __shared__ float red[8];
        if ((tid & 31) == 0) red[tid >> 5] = s;
        __syncthreads();
        if ((tid & 63) == 0) {
            int w0 = tid >> 5;
            g_t1[b] = red[w0] + red[w0 + 1];
        }
    } else {
        // 2 cp rows per block; thread t: cp = base + t/128, 4 elems
        int cp = (blockIdx.x - 256) * 2 + (tid >> 7);
        int d0 = (tid & 127) * 4;
        float4 lw = *reinterpret_cast<const float4*>(ls + (size_t)cp * 512 + d0);
        float4 pv = *reinterpret_cast<const float4*>(proto + (size_t)cp * 512 + d0);
        bool nzb = (lw.x != 0.f) || (lw.y != 0.f) || (lw.z != 0.f) || (lw.w != 0.f);
        unsigned nz = __ballot_sync(0xffffffffu, nzb);
        if (nz && (tid & 31) == 0) atomicOr(&g_flag, 1);   // sticky across replays
        float w0 = expf(lw.x), w1 = expf(lw.y), w2 = expf(lw.z), w3 = expf(lw.w);
        __nv_bfloat162 hw[2], hp[2];
        hw[0] = __floats2bfloat162_rn(w0, w1);
        hw[1] = __floats2bfloat162_rn(w2, w3);
        hp[0] = __floats2bfloat162_rn(-2.0f * w0 * pv.x, -2.0f * w1 * pv.y);
        hp[1] = __floats2bfloat162_rn(-2.0f * w2 * pv.z, -2.0f * w3 * pv.w);
        *reinterpret_cast<uint2*>(g_Bm + (size_t)cp * KD + d0)       = *reinterpret_cast<uint2*>(hw);
        *reinterpret_cast<uint2*>(g_Bm + (size_t)cp * KD + 512 + d0) = *reinterpret_cast<uint2*>(hp);
        float acc = w0 * pv.x * pv.x + w1 * pv.y * pv.y + w2 * pv.z * pv.z + w3 * pv.w * pv.w;
        #pragma unroll
        for (int o = 16; o > 0; o >>= 1) acc += __shfl_xor_sync(0xffffffffu, acc, o);
        __shared__ float red2[8];
        if ((tid & 31) == 0) red2[tid >> 5] = acc;
        __syncthreads();
        if ((tid & 127) == 0) {
            int w0i = (tid >> 7) * 4;
            g_t3[cp] = red2[w0i] + red2[w0i + 1] + red2[w0i + 2] + red2[w0i + 3];
        }
    }
}

// ---------------- GEMM + fused LSE (R8, unchanged) ----------------
// SMEM: A[2][256][64] bf16 (SW128, 32KB each), B[2][40][64] bf16 (5KB each)
#define SA_OFF(buf) ((buf) * 32768)
#define SB_OFF(buf) (65536 + (buf) * 5120)
#define SMEM_TOTAL  (65536 + 2 * 5120)      // 75776
#define SST_STRIDE  44
#define T3_OFF      (256 * SST_STRIDE * 4)  // 45056

__global__ __launch_bounds__(256, 1) void gemm_lse_kernel(float* __restrict__ out) {
    extern __shared__ char smem[];
    const uint32_t sbase = smem_u32(smem);
    const int tid = threadIdx.x;
    const int wid = tid >> 5;
    const int lid = tid & 31;
    const int m0 = blockIdx.y * BM;
    const int n0 = blockIdx.x * BN;

    const int flag = g_flag;
    const int kstart = flag ? 0 : 8;   // fast path: only the x-part (k 512..1023)

    const __nv_bfloat16* a_src[8];
    uint32_t a_dst[8];
    #pragma unroll
    for (int i = 0; i < 8; i++) {
        int q = tid + i * 256;
        int r = q >> 3, c = q & 7;
        a_src[i] = g_A + (size_t)(m0 + r) * KD + c * 8;
        a_dst[i] = sw128((uint32_t)r * 128u + (uint32_t)c * 16u);
    }
    const __nv_bfloat16* b_src[2];
    uint32_t b_dst[2];
    bool b_ok[2];
    #pragma unroll
    for (int i = 0; i < 2; i++) {
        int q = tid + i * 256;
        int r = q >> 3, c = q & 7;
        b_ok[i] = (q < 320);
        b_src[i] = g_Bm + (size_t)(n0 + (b_ok[i] ? r : 0)) * KD + c * 8;
        b_dst[i] = sw128((uint32_t)(b_ok[i] ? r : 0) * 128u + (uint32_t)c * 16u);
    }

    const int wm = wid * 32;

    float acc[2][5][4];
    #pragma unroll
    for (int mf = 0; mf < 2; mf++)
        #pragma unroll
        for (int nf = 0; nf < 5; nf++)
            #pragma unroll
            for (int i = 0; i < 4; i++) acc[mf][nf][i] = 0.f;

    const int l4 = lid & 15;
    uint32_t a_lm_off[2][4];
    uint32_t b_lm_off[5][4];
    #pragma unroll
    for (int mf = 0; mf < 2; mf++)
        #pragma unroll
        for (int ks = 0; ks < 4; ks++) {
            uint32_t r = wm + mf * 16 + (lid & 15);
            uint32_t ch = ks * 2 + (lid >> 4);
            a_lm_off[mf][ks] = sw128(r * 128u + ch * 16u);
        }
    #pragma unroll
    for (int nf = 0; nf < 5; nf++)
        #pragma unroll
        for (int ks = 0; ks < 4; ks++) {
            uint32_t r = nf * 8 + (l4 & 7);
            uint32_t ch = ks * 2 + (l4 >> 3);
            b_lm_off[nf][ks] = sw128(r * 128u + ch * 16u);
        }

    {
        int buf = kstart & 1;
        uint32_t sa = sbase + SA_OFF(buf), sb = sbase + SB_OFF(buf);
        #pragma unroll
        for (int i = 0; i < 8; i++) CP_ASYNC16(sa + a_dst[i], a_src[i] + kstart * BK);
        #pragma unroll
        for (int i = 0; i < 2; i++) if (b_ok[i]) CP_ASYNC16(sb + b_dst[i], b_src[i] + kstart * BK);
        CP_COMMIT();
    }

    for (int kt = kstart; kt < NKT; kt++) {
        if (kt + 1 < NKT) {
            int nb = (kt + 1) & 1;
            uint32_t sa = sbase + SA_OFF(nb), sb = sbase + SB_OFF(nb);
            #pragma unroll
            for (int i = 0; i < 8; i++) CP_ASYNC16(sa + a_dst[i], a_src[i] + (kt + 1) * BK);
            #pragma unroll
            for (int i = 0; i < 2; i++) if (b_ok[i]) CP_ASYNC16(sb + b_dst[i], b_src[i] + (kt + 1) * BK);
            CP_COMMIT();
            CP_WAIT1();
        } else {
            CP_WAIT0();
        }
        __syncthreads();

        const uint32_t sa = sbase + SA_OFF(kt & 1);
        const uint32_t sb = sbase + SB_OFF(kt & 1);
        #pragma unroll
        for (int ks = 0; ks < 4; ks++) {
            uint32_t a[2][4], b[5][2];
            #pragma unroll
            for (int mf = 0; mf < 2; mf++)
                LDMATRIX_X4(a[mf][0], a[mf][1], a[mf][2], a[mf][3], sa + a_lm_off[mf][ks]);
            #pragma unroll
            for (int nf = 0; nf < 5; nf++)
                LDMATRIX_X2(b[nf][0], b[nf][1], sb + b_lm_off[nf][ks]);
            #pragma unroll
            for (int mf = 0; mf < 2; mf++)
                #pragma unroll
                for (int nf = 0; nf < 5; nf++)
                    MMA_16816(acc[mf][nf][0], acc[mf][nf][1], acc[mf][nf][2], acc[mf][nf][3],
                              a[mf][0], a[mf][1], a[mf][2], a[mf][3], b[nf][0], b[nf][1]);
        }
        __syncthreads();
    }

    // ---- fused epilogue ----
    float* sst = reinterpret_cast<float*>(smem);            // [256][44]
    float* st3 = reinterpret_cast<float*>(smem + T3_OFF);   // [40]
    if (tid < 40) st3[tid] = g_t3[n0 + tid];

    const int qr = lid >> 2;
    const int qc = (lid & 3) * 2;
    #pragma unroll
    for (int mf = 0; mf < 2; mf++) {
        int row = wm + mf * 16 + qr;
        #pragma unroll
        for (int nf = 0; nf < 5; nf++) {
            int col = nf * 8 + qc;
            *reinterpret_cast<float2*>(&sst[row * SST_STRIDE + col]) =
                make_float2(acc[mf][nf][0], acc[mf][nf][1]);
            *reinterpret_cast<float2*>(&sst[(row + 8) * SST_STRIDE + col]) =
                make_float2(acc[mf][nf][2], acc[mf][nf][3]);
        }
    }
    __syncthreads();

    const int c0 = blockIdx.x * 4;
    #pragma unroll
    for (int i = 0; i < 4; i++) {
        int task = tid + i * 256;
        int row = task >> 2;
        int cls = task & 3;
        const float* sp = &sst[row * SST_STRIDE + cls * 10];
        const float* tp = &st3[cls * 10];
        float v[10], mx = -3.4e38f;
        #pragma unroll
        for (int p = 0; p < 10; p++) {
            v[p] = -(sp[p] + tp[p]);
            mx = fmaxf(mx, v[p]);
        }
        float s = 0.f;
        #pragma unroll
        for (int p = 0; p < 10; p++) s += expf(v[p] - mx);
        float t1v = flag ? 0.f : g_t1[m0 + row];   // fast path: t1 slid out of lse
        out[(size_t)(m0 + row) * 100 + c0 + cls] = mx + logf(s) - t1v;
    }
}

// ---------------- launch ----------------
extern "C" void kernel_launch(void* const* d_in, const int* in_sizes, int n_in,
                              void* d_out, int out_size) {
    const float* x     = (const float*)d_in[0];  // (1024, 512)
    const float* proto = (const float*)d_in[1];  // (100, 10, 512)
    const float* ls    = (const float*)d_in[2];  // (100, 10, 512)
    float* out = (float*)d_out;                  // (1024, 100)

    cudaFuncSetAttribute(gemm_lse_kernel, cudaFuncAttributeMaxDynamicSharedMemorySize, SMEM_TOTAL);

    prep_kernel<<<756, 256>>>(x, proto, ls);     // x+t1 (256 blocks) | proto+t3+flag (500)
    gemm_lse_kernel<<<dim3(25, MB / BM), 256, SMEM_TOTAL>>>(out);
}

// round 10
// speedup vs baseline: 1.5804x; 1.0402x over previous
#include <cuda_runtime.h>
#include <cuda_bf16.h>
#include <cstdint>
#include <math.h>

// ============================================================
// x(1024,512) f32, prototypes(100,10,512) f32, log_dist_scales(100,10,512) f32
// out(1024,100) = logsumexp_p( -( sum_d w*(x-p)^2 ) ),  w = exp(ls)
// dist = t1 + (-2*t2 + t3)
// R10: tile-granularity fix. BM=64/BN=40, 128-thread CTAs, grid 16x25=400
// tiles -> per-SM critical path W/133 vs R9's W/100 (48 idle SMs). 4 CTAs/SM
// co-resident. Fast path (ls==0): K=512, t1 slid out of LSE (R8/R9 proven).
// ============================================================

#define MB 1024
#define KD 1024

#define BM 64
#define BN 40
#define BK 64
#define NKT (KD / BK)   // 16
#define NTHREADS 128

// ---------------- device scratch ----------------
__device__ __nv_bfloat16 g_A[MB * KD];     // [b][k]  k<512: x^2, k>=512: x
__device__ __nv_bfloat16 g_Bm[1000 * KD];  // [cp][k] k<512: w,   k>=512: -2wp
__device__ float g_t3[1000];               // sum w p^2
__device__ float g_t1[MB];                 // sum x^2 (fp32 exact)
__device__ int   g_flag;                   // sticky: 1 if any ls != 0 (zero-init)

// ---------------- helpers ----------------
__device__ __forceinline__ uint32_t smem_u32(const void* p) {
    uint32_t a;
    asm("{ .reg .u64 t; cvta.to.shared.u64 t, %1; cvt.u32.u64 %0, t; }" : "=r"(a) : "l"(p));
    return a;
}
__device__ __forceinline__ uint32_t sw128(uint32_t off) {
    return off ^ ((off >> 3) & 0x70);
}
#define CP_ASYNC16(dst, src) \
    asm volatile("cp.async.cg.shared.global [%0], [%1], 16;" :: "r"(dst), "l"(src) : "memory")
#define CP_COMMIT() asm volatile("cp.async.commit_group;" ::: "memory")
#define CP_WAIT1()  asm volatile("cp.async.wait_group 1;" ::: "memory")
#define CP_WAIT0()  asm volatile("cp.async.wait_group 0;" ::: "memory")

#define LDMATRIX_X4(r0, r1, r2, r3, addr) \
    asm volatile("ldmatrix.sync.aligned.m8n8.x4.shared.b16 {%0,%1,%2,%3}, [%4];" \
                 : "=r"(r0), "=r"(r1), "=r"(r2), "=r"(r3) : "r"(addr))
#define LDMATRIX_X2(r0, r1, addr) \
    asm volatile("ldmatrix.sync.aligned.m8n8.x2.shared.b16 {%0,%1}, [%2];" \
                 : "=r"(r0), "=r"(r1) : "r"(addr))
#define MMA_16816(c0, c1, c2, c3, a0, a1, a2, a3, b0, b1) \
    asm volatile("mma.sync.aligned.m16n8k16.row.col.f32.bf16.bf16.f32 " \
                 "{%0,%1,%2,%3}, {%4,%5,%6,%7}, {%8,%9}, {%0,%1,%2,%3};" \
                 : "+f"(c0), "+f"(c1), "+f"(c2), "+f"(c3) \
                 : "r"(a0), "r"(a1), "r"(a2), "r"(a3), "r"(b0), "r"(b1))

// ---------------- prep: x + t1 (blocks 0..255), proto + t3 + flag (blocks 256..755)
__global__ void prep_kernel(const float* __restrict__ x,
                            const float* __restrict__ proto,
                            const float* __restrict__ ls) {
    const int tid = threadIdx.x;
    if (blockIdx.x < 256) {
        int idx = blockIdx.x * 256 + tid;
        int b  = idx >> 6;
        int d0 = (idx & 63) * 8;
        const float4* src = reinterpret_cast<const float4*>(x) + idx * 2;
        float4 v0 = src[0], v1 = src[1];
        __nv_bfloat162 hs[4], hx[4];
        hs[0] = __floats2bfloat162_rn(v0.x * v0.x, v0.y * v0.y);
        hs[1] = __floats2bfloat162_rn(v0.z * v0.z, v0.w * v0.w);
        hs[2] = __floats2bfloat162_rn(v1.x * v1.x, v1.y * v1.y);
        hs[3] = __floats2bfloat162_rn(v1.z * v1.z, v1.w * v1.w);
        hx[0] = __floats2bfloat162_rn(v0.x, v0.y);
        hx[1] = __floats2bfloat162_rn(v0.z, v0.w);
        hx[2] = __floats2bfloat162_rn(v1.x, v1.y);
        hx[3] = __floats2bfloat162_rn(v1.z, v1.w);
        *reinterpret_cast<uint4*>(g_A + (size_t)b * KD + d0)       = *reinterpret_cast<uint4*>(hs);
        *reinterpret_cast<uint4*>(g_A + (size_t)b * KD + 512 + d0) = *reinterpret_cast<uint4*>(hx);
        float s = v0.x * v0.x + v0.y * v0.y + v0.z * v0.z + v0.w * v0.w
                + v1.x * v1.x + v1.y * v1.y + v1.z * v1.z + v1.w * v1.w;
        #pragma unroll
        for (int o = 16; o > 0; o >>= 1) s += __shfl_xor_sync(0xffffffffu, s, o);
        __shared__ float red[8];
        if ((tid & 31) == 0) red[tid >> 5] = s;
        __syncthreads();
        if ((tid & 63) == 0) {
            int w0 = tid >> 5;
            g_t1[b] = red[w0] + red[w0 + 1];
        }
    } else {
        int cp = (blockIdx.x - 256) * 2 + (tid >> 7);
        int d0 = (tid & 127) * 4;
        float4 lw = *reinterpret_cast<const float4*>(ls + (size_t)cp * 512 + d0);
        float4 pv = *reinterpret_cast<const float4*>(proto + (size_t)cp * 512 + d0);
        bool nzb = (lw.x != 0.f) || (lw.y != 0.f) || (lw.z != 0.f) || (lw.w != 0.f);
        unsigned nz = __ballot_sync(0xffffffffu, nzb);
        if (nz && (tid & 31) == 0) atomicOr(&g_flag, 1);   // sticky across replays
        float w0 = expf(lw.x), w1 = expf(lw.y), w2 = expf(lw.z), w3 = expf(lw.w);
        __nv_bfloat162 hw[2], hp[2];
        hw[0] = __floats2bfloat162_rn(w0, w1);
        hw[1] = __floats2bfloat162_rn(w2, w3);
        hp[0] = __floats2bfloat162_rn(-2.0f * w0 * pv.x, -2.0f * w1 * pv.y);
        hp[1] = __floats2bfloat162_rn(-2.0f * w2 * pv.z, -2.0f * w3 * pv.w);
        *reinterpret_cast<uint2*>(g_Bm + (size_t)cp * KD + d0)       = *reinterpret_cast<uint2*>(hw);
        *reinterpret_cast<uint2*>(g_Bm + (size_t)cp * KD + 512 + d0) = *reinterpret_cast<uint2*>(hp);
        float acc = w0 * pv.x * pv.x + w1 * pv.y * pv.y + w2 * pv.z * pv.z + w3 * pv.w * pv.w;
        #pragma unroll
        for (int o = 16; o > 0; o >>= 1) acc += __shfl_xor_sync(0xffffffffu, acc, o);
        __shared__ float red2[8];
        if ((tid & 31) == 0) red2[tid >> 5] = acc;
        __syncthreads();
        if ((tid & 127) == 0) {
            int w0i = (tid >> 7) * 4;
            g_t3[cp] = red2[w0i] + red2[w0i + 1] + red2[w0i + 2] + red2[w0i + 3];
        }
    }
}

// ---------------- GEMM + fused LSE: BM=64, BN=40, 128 threads ----------------
// SMEM: A[2][64][64] bf16 (SW128, 8KB each), B[2][40][64] bf16 (5KB each) = 26KB
#define SA_OFF(buf) ((buf) * 8192)
#define SB_OFF(buf) (16384 + (buf) * 5120)
#define SMEM_TOTAL  (16384 + 2 * 5120)      // 26624
#define SST_STRIDE  44
#define T3_OFF      (64 * SST_STRIDE * 4)   // 11264 (inside A region, used post-loop)

__global__ __launch_bounds__(NTHREADS, 4) void gemm_lse_kernel(float* __restrict__ out) {
    extern __shared__ char smem[];
    const uint32_t sbase = smem_u32(smem);
    const int tid = threadIdx.x;
    const int wid = tid >> 5;    // 0..3
    const int lid = tid & 31;
    const int m0 = blockIdx.y * BM;
    const int n0 = blockIdx.x * BN;

    const int flag = g_flag;
    const int kstart = flag ? 0 : 8;   // fast path: only the x-part (k 512..1023)

    // ---- load plan: A 512 chunks (4/thread); B 320 chunks (3/thread, guarded)
    const __nv_bfloat16* a_src[4];
    uint32_t a_dst[4];
    #pragma unroll
    for (int i = 0; i < 4; i++) {
        int q = tid + i * NTHREADS;
        int r = q >> 3, c = q & 7;
        a_src[i] = g_A + (size_t)(m0 + r) * KD + c * 8;
        a_dst[i] = sw128((uint32_t)r * 128u + (uint32_t)c * 16u);
    }
    const __nv_bfloat16* b_src[3];
    uint32_t b_dst[3];
    bool b_ok[3];
    #pragma unroll
    for (int i = 0; i < 3; i++) {
        int q = tid + i * NTHREADS;
        int r = q >> 3, c = q & 7;
        b_ok[i] = (q < 320);
        b_src[i] = g_Bm + (size_t)(n0 + (b_ok[i] ? r : 0)) * KD + c * 8;
        b_dst[i] = sw128((uint32_t)(b_ok[i] ? r : 0) * 128u + (uint32_t)c * 16u);
    }

    // warp layout: 4 warps stacked in M; warp tile 16 x 40
    const int wm = wid * 16;

    float acc[5][4];
    #pragma unroll
    for (int nf = 0; nf < 5; nf++)
        #pragma unroll
        for (int i = 0; i < 4; i++) acc[nf][i] = 0.f;

    const int l4 = lid & 15;
    uint32_t a_lm_off[4];
    uint32_t b_lm_off[5][4];
    #pragma unroll
    for (int ks = 0; ks < 4; ks++) {
        uint32_t r = wm + (lid & 15);
        uint32_t ch = ks * 2 + (lid >> 4);
        a_lm_off[ks] = sw128(r * 128u + ch * 16u);
    }
    #pragma unroll
    for (int nf = 0; nf < 5; nf++)
        #pragma unroll
        for (int ks = 0; ks < 4; ks++) {
            uint32_t r = nf * 8 + (l4 & 7);
            uint32_t ch = ks * 2 + (l4 >> 3);
            b_lm_off[nf][ks] = sw128(r * 128u + ch * 16u);
        }

    // ---- prologue: tile kstart ----
    {
        int buf = kstart & 1;
        uint32_t sa = sbase + SA_OFF(buf), sb = sbase + SB_OFF(buf);
        #pragma unroll
        for (int i = 0; i < 4; i++) CP_ASYNC16(sa + a_dst[i], a_src[i] + kstart * BK);
        #pragma unroll
        for (int i = 0; i < 3; i++) if (b_ok[i]) CP_ASYNC16(sb + b_dst[i], b_src[i] + kstart * BK);
        CP_COMMIT();
    }

    for (int kt = kstart; kt < NKT; kt++) {
        if (kt + 1 < NKT) {
            int nb = (kt + 1) & 1;
            uint32_t sa = sbase + SA_OFF(nb), sb = sbase + SB_OFF(nb);
            #pragma unroll
            for (int i = 0; i < 4; i++) CP_ASYNC16(sa + a_dst[i], a_src[i] + (kt + 1) * BK);
            #pragma unroll
            for (int i = 0; i < 3; i++) if (b_ok[i]) CP_ASYNC16(sb + b_dst[i], b_src[i] + (kt + 1) * BK);
            CP_COMMIT();
            CP_WAIT1();
        } else {
            CP_WAIT0();
        }
        __syncthreads();

        const uint32_t sa = sbase + SA_OFF(kt & 1);
        const uint32_t sb = sbase + SB_OFF(kt & 1);
        #pragma unroll
        for (int ks = 0; ks < 4; ks++) {
            uint32_t a[4], b[5][2];
            LDMATRIX_X4(a[0], a[1], a[2], a[3], sa + a_lm_off[ks]);
            #pragma unroll
            for (int nf = 0; nf < 5; nf++)
                LDMATRIX_X2(b[nf][0], b[nf][1], sb + b_lm_off[nf][ks]);
            #pragma unroll
            for (int nf = 0; nf < 5; nf++)
                MMA_16816(acc[nf][0], acc[nf][1], acc[nf][2], acc[nf][3],
                          a[0], a[1], a[2], a[3], b[nf][0], b[nf][1]);
        }
        __syncthreads();
    }

    // ---- fused epilogue: fragments -> SMEM stage -> per-(row,class) logsumexp ----
    float* sst = reinterpret_cast<float*>(smem);            // [64][44]
    float* st3 = reinterpret_cast<float*>(smem + T3_OFF);   // [40]
    if (tid < 40) st3[tid] = g_t3[n0 + tid];

    const int qr = lid >> 2;
    const int qc = (lid & 3) * 2;
    {
        int row = wm + qr;
        #pragma unroll
        for (int nf = 0; nf < 5; nf++) {
            int col = nf * 8 + qc;
            *reinterpret_cast<float2*>(&sst[row * SST_STRIDE + col]) =
                make_float2(acc[nf][0], acc[nf][1]);
            *reinterpret_cast<float2*>(&sst[(row + 8) * SST_STRIDE + col]) =
                make_float2(acc[nf][2], acc[nf][3]);
        }
    }
    __syncthreads();

    // 64 rows x 4 classes = 256 tasks, 2 per thread
    const int c0 = blockIdx.x * 4;
    #pragma unroll
    for (int i = 0; i < 2; i++) {
        int task = tid + i * NTHREADS;
        int row = task >> 2;
        int cls = task & 3;
        const float* sp = &sst[row * SST_STRIDE + cls * 10];
        const float* tp = &st3[cls * 10];
        float v[10], mx = -3.4e38f;
        #pragma unroll
        for (int p = 0; p < 10; p++) {
            v[p] = -(sp[p] + tp[p]);
            mx = fmaxf(mx, v[p]);
        }
        float s = 0.f;
        #pragma unroll
        for (int p = 0; p < 10; p++) s += expf(v[p] - mx);
        float t1v = flag ? 0.f : g_t1[m0 + row];   // fast path: t1 slid out of lse
        out[(size_t)(m0 + row) * 100 + c0 + cls] = mx + logf(s) - t1v;
    }
}

// ---------------- launch ----------------
extern "C" void kernel_launch(void* const* d_in, const int* in_sizes, int n_in,
                              void* d_out, int out_size) {
    const float* x     = (const float*)d_in[0];  // (1024, 512)
    const float* proto = (const float*)d_in[1];  // (100, 10, 512)
    const float* ls    = (const float*)d_in[2];  // (100, 10, 512)
    float* out = (float*)d_out;                  // (1024, 100)

    cudaFuncSetAttribute(gemm_lse_kernel, cudaFuncAttributeMaxDynamicSharedMemorySize, SMEM_TOTAL);

    prep_kernel<<<756, 256>>>(x, proto, ls);     // x+t1 (256 blocks) | proto+t3+flag (500)
    gemm_lse_kernel<<<dim3(25, MB / BM), NTHREADS, SMEM_TOTAL>>>(out);
}

// round 11
// speedup vs baseline: 1.7019x; 1.0769x over previous
#include <cuda_runtime.h>
#include <cuda_bf16.h>
#include <cstdint>
#include <math.h>

// ============================================================
// x(1024,512) f32, prototypes(100,10,512) f32, log_dist_scales(100,10,512) f32
// out(1024,100) = logsumexp_p( -( sum_d w*(x-p)^2 ) ),  w = exp(ls)
// dist = t1 + (-2*t2 + t3)
// R11: intra-tile latency fix on R10's 400-tile layout. Register fragment
// double-buffer (ks+1 LDSM overlapped with ks MMAs), 3-stage SMEM pipeline
// with ONE sync/iter, batched B ldmatrix (2 x4 + 1 x2). (128,3) bounds.
// Fast path (ls==0): K=512, t1 slid out of LSE.
// ============================================================

#define MB 1024
#define KD 1024

#define BM 64
#define BN 40
#define BK 64
#define NKT (KD / BK)   // 16
#define NTHREADS 128

// ---------------- device scratch ----------------
__device__ __nv_bfloat16 g_A[MB * KD];     // [b][k]  k<512: x^2, k>=512: x
__device__ __nv_bfloat16 g_Bm[1000 * KD];  // [cp][k] k<512: w,   k>=512: -2wp
__device__ float g_t3[1000];               // sum w p^2
__device__ float g_t1[MB];                 // sum x^2 (fp32 exact)
__device__ int   g_flag;                   // sticky: 1 if any ls != 0 (zero-init)

// ---------------- helpers ----------------
__device__ __forceinline__ uint32_t smem_u32(const void* p) {
    uint32_t a;
    asm("{ .reg .u64 t; cvta.to.shared.u64 t, %1; cvt.u32.u64 %0, t; }" : "=r"(a) : "l"(p));
    return a;
}
__device__ __forceinline__ uint32_t sw128(uint32_t off) {
    return off ^ ((off >> 3) & 0x70);
}
#define CP_ASYNC16(dst, src) \
    asm volatile("cp.async.cg.shared.global [%0], [%1], 16;" :: "r"(dst), "l"(src) : "memory")
#define CP_COMMIT() asm volatile("cp.async.commit_group;" ::: "memory")
#define CP_WAIT1()  asm volatile("cp.async.wait_group 1;" ::: "memory")
#define CP_WAIT0()  asm volatile("cp.async.wait_group 0;" ::: "memory")

#define LDMATRIX_X4(r0, r1, r2, r3, addr) \
    asm volatile("ldmatrix.sync.aligned.m8n8.x4.shared.b16 {%0,%1,%2,%3}, [%4];" \
                 : "=r"(r0), "=r"(r1), "=r"(r2), "=r"(r3) : "r"(addr))
#define LDMATRIX_X2(r0, r1, addr) \
    asm volatile("ldmatrix.sync.aligned.m8n8.x2.shared.b16 {%0,%1}, [%2];" \
                 : "=r"(r0), "=r"(r1) : "r"(addr))
#define MMA_16816(c0, c1, c2, c3, a0, a1, a2, a3, b0, b1) \
    asm volatile("mma.sync.aligned.m16n8k16.row.col.f32.bf16.bf16.f32 " \
                 "{%0,%1,%2,%3}, {%4,%5,%6,%7}, {%8,%9}, {%0,%1,%2,%3};" \
                 : "+f"(c0), "+f"(c1), "+f"(c2), "+f"(c3) \
                 : "r"(a0), "r"(a1), "r"(a2), "r"(a3), "r"(b0), "r"(b1))

// ---------------- prep: x + t1 (blocks 0..255), proto + t3 + flag (blocks 256..755)
__global__ void prep_kernel(const float* __restrict__ x,
                            const float* __restrict__ proto,
                            const float* __restrict__ ls) {
    const int tid = threadIdx.x;
    if (blockIdx.x < 256) {
        int idx = blockIdx.x * 256 + tid;
        int b  = idx >> 6;
        int d0 = (idx & 63) * 8;
        const float4* src = reinterpret_cast<const float4*>(x) + idx * 2;
        float4 v0 = src[0], v1 = src[1];
        __nv_bfloat162 hs[4], hx[4];
        hs[0] = __floats2bfloat162_rn(v0.x * v0.x, v0.y * v0.y);
        hs[1] = __floats2bfloat162_rn(v0.z * v0.z, v0.w * v0.w);
        hs[2] = __floats2bfloat162_rn(v1.x * v1.x, v1.y * v1.y);
        hs[3] = __floats2bfloat162_rn(v1.z * v1.z, v1.w * v1.w);
        hx[0] = __floats2bfloat162_rn(v0.x, v0.y);
        hx[1] = __floats2bfloat162_rn(v0.z, v0.w);
        hx[2] = __floats2bfloat162_rn(v1.x, v1.y);
        hx[3] = __floats2bfloat162_rn(v1.z, v1.w);
        *reinterpret_cast<uint4*>(g_A + (size_t)b * KD + d0)       = *reinterpret_cast<uint4*>(hs);
        *reinterpret_cast<uint4*>(g_A + (size_t)b * KD + 512 + d0) = *reinterpret_cast<uint4*>(hx);
        float s = v0.x * v0.x + v0.y * v0.y + v0.z * v0.z + v0.w * v0.w
                + v1.x * v1.x + v1.y * v1.y + v1.z * v1.z + v1.w * v1.w;
        #pragma unroll
        for (int o = 16; o > 0; o >>= 1) s += __shfl_xor_sync(0xffffffffu, s, o);
        __shared__ float red[8];
        if ((tid & 31) == 0) red[tid >> 5] = s;
        __syncthreads();
        if ((tid & 63) == 0) {
            int w0 = tid >> 5;
            g_t1[b] = red[w0] + red[w0 + 1];
        }
    } else {
        int cp = (blockIdx.x - 256) * 2 + (tid >> 7);
        int d0 = (tid & 127) * 4;
        float4 lw = *reinterpret_cast<const float4*>(ls + (size_t)cp * 512 + d0);
        float4 pv = *reinterpret_cast<const float4*>(proto + (size_t)cp * 512 + d0);
        bool nzb = (lw.x != 0.f) || (lw.y != 0.f) || (lw.z != 0.f) || (lw.w != 0.f);
        unsigned nz = __ballot_sync(0xffffffffu, nzb);
        if (nz && (tid & 31) == 0) atomicOr(&g_flag, 1);   // sticky across replays
        float w0 = expf(lw.x), w1 = expf(lw.y), w2 = expf(lw.z), w3 = expf(lw.w);
        __nv_bfloat162 hw[2], hp[2];
        hw[0] = __floats2bfloat162_rn(w0, w1);
        hw[1] = __floats2bfloat162_rn(w2, w3);
        hp[0] = __floats2bfloat162_rn(-2.0f * w0 * pv.x, -2.0f * w1 * pv.y);
        hp[1] = __floats2bfloat162_rn(-2.0f * w2 * pv.z, -2.0f * w3 * pv.w);
        *reinterpret_cast<uint2*>(g_Bm + (size_t)cp * KD + d0)       = *reinterpret_cast<uint2*>(hw);
        *reinterpret_cast<uint2*>(g_Bm + (size_t)cp * KD + 512 + d0) = *reinterpret_cast<uint2*>(hp);
        float acc = w0 * pv.x * pv.x + w1 * pv.y * pv.y + w2 * pv.z * pv.z + w3 * pv.w * pv.w;
        #pragma unroll
        for (int o = 16; o > 0; o >>= 1) acc += __shfl_xor_sync(0xffffffffu, acc, o);
        __shared__ float red2[8];
        if ((tid & 31) == 0) red2[tid >> 5] = acc;
        __syncthreads();
        if ((tid & 127) == 0) {
            int w0i = (tid >> 7) * 4;
            g_t3[cp] = red2[w0i] + red2[w0i + 1] + red2[w0i + 2] + red2[w0i + 3];
        }
    }
}

// ---------------- GEMM + fused LSE: BM=64, BN=40, 128 threads, 3-stage ----------------
// SMEM: A[3][64][64] bf16 (8KB/stage), B[3][40][64] bf16 (5KB/stage) = 39KB
#define SA_OFF(s) ((s) * 8192)
#define SB_OFF(s) (24576 + (s) * 5120)
#define SMEM_TOTAL  (24576 + 3 * 5120)      // 39936
#define SST_STRIDE  44
#define T3_OFF      (64 * SST_STRIDE * 4)   // 11264 (inside A region, post-loop use)

__global__ __launch_bounds__(NTHREADS, 3) void gemm_lse_kernel(float* __restrict__ out) {
    extern __shared__ char smem[];
    const uint32_t sbase = smem_u32(smem);
    const int tid = threadIdx.x;
    const int wid = tid >> 5;    // 0..3
    const int lid = tid & 31;
    const int m0 = blockIdx.y * BM;
    const int n0 = blockIdx.x * BN;

    const int flag = g_flag;
    const int kstart = flag ? 0 : 8;   // fast path: only the x-part (k 512..1023)

    // ---- load plan: A 512 chunks (4/thread); B 320 chunks (3/thread, guarded)
    const __nv_bfloat16* a_src[4];
    uint32_t a_dst[4];
    #pragma unroll
    for (int i = 0; i < 4; i++) {
        int q = tid + i * NTHREADS;
        int r = q >> 3, c = q & 7;
        a_src[i] = g_A + (size_t)(m0 + r) * KD + c * 8;
        a_dst[i] = sw128((uint32_t)r * 128u + (uint32_t)c * 16u);
    }
    const __nv_bfloat16* b_src[3];
    uint32_t b_dst[3];
    bool b_ok[3];
    #pragma unroll
    for (int i = 0; i < 3; i++) {
        int q = tid + i * NTHREADS;
        int r = q >> 3, c = q & 7;
        b_ok[i] = (q < 320);
        b_src[i] = g_Bm + (size_t)(n0 + (b_ok[i] ? r : 0)) * KD + c * 8;
        b_dst[i] = sw128((uint32_t)(b_ok[i] ? r : 0) * 128u + (uint32_t)c * 16u);
    }

    // warp layout: 4 warps stacked in M; warp tile 16 x 40
    const int wm = wid * 16;

    float acc[5][4];
    #pragma unroll
    for (int nf = 0; nf < 5; nf++)
        #pragma unroll
        for (int i = 0; i < 4; i++) acc[nf][i] = 0.f;

    // ldmatrix swizzled offsets: A x4; B as 2 x4 (nf pairs) + 1 x2 (nf=4)
    const int l4 = lid & 15;
    uint32_t a_lm_off[4];
    uint32_t b4_off[2][4];
    uint32_t b2_off[4];
    #pragma unroll
    for (int ks = 0; ks < 4; ks++) {
        {
            uint32_t r = wm + (lid & 15);
            uint32_t ch = ks * 2 + (lid >> 4);
            a_lm_off[ks] = sw128(r * 128u + ch * 16u);
        }
        #pragma unroll
        for (int j = 0; j < 2; j++) {
            uint32_t r = j * 16 + (lid >> 4) * 8 + (lid & 7);
            uint32_t ch = ks * 2 + ((lid >> 3) & 1);
            b4_off[j][ks] = sw128(r * 128u + ch * 16u);
        }
        {
            uint32_t r = 32 + (l4 & 7);
            uint32_t ch = ks * 2 + (l4 >> 3);
            b2_off[ks] = sw128(r * 128u + ch * 16u);
        }
    }

    // ---- prologue: stages kstart, kstart+1 ----
    #pragma unroll
    for (int s = 0; s < 2; s++) {
        int kt = kstart + s;
        uint32_t sa = sbase + SA_OFF(kt % 3), sb = sbase + SB_OFF(kt % 3);
        #pragma unroll
        for (int i = 0; i < 4; i++) CP_ASYNC16(sa + a_dst[i], a_src[i] + kt * BK);
        #pragma unroll
        for (int i = 0; i < 3; i++) if (b_ok[i]) CP_ASYNC16(sb + b_dst[i], b_src[i] + kt * BK);
        CP_COMMIT();
    }

    for (int kt = kstart; kt < NKT; kt++) {
        if (kt + 1 < NKT) CP_WAIT1(); else CP_WAIT0();
        __syncthreads();   // single barrier per iter (3-stage reuse distance)

        if (kt + 2 < NKT) {
            int ns = (kt + 2) % 3;
            uint32_t sa = sbase + SA_OFF(ns), sb = sbase + SB_OFF(ns);
            #pragma unroll
            for (int i = 0; i < 4; i++) CP_ASYNC16(sa + a_dst[i], a_src[i] + (kt + 2) * BK);
            #pragma unroll
            for (int i = 0; i < 3; i++) if (b_ok[i]) CP_ASYNC16(sb + b_dst[i], b_src[i] + (kt + 2) * BK);
            CP_COMMIT();
        }

        const uint32_t sa = sbase + SA_OFF(kt % 3);
        const uint32_t sb = sbase + SB_OFF(kt % 3);

        // register fragment double-buffer across ks
        uint32_t fa[2][4], fb[2][5][2];
        LDMATRIX_X4(fa[0][0], fa[0][1], fa[0][2], fa[0][3], sa + a_lm_off[0]);
        LDMATRIX_X4(fb[0][0][0], fb[0][0][1], fb[0][1][0], fb[0][1][1], sb + b4_off[0][0]);
        LDMATRIX_X4(fb[0][2][0], fb[0][2][1], fb[0][3][0], fb[0][3][1], sb + b4_off[1][0]);
        LDMATRIX_X2(fb[0][4][0], fb[0][4][1], sb + b2_off[0]);
        #pragma unroll
        for (int ks = 0; ks < 4; ks++) {
            const int cur = ks & 1, nxt = cur ^ 1;
            if (ks < 3) {
                LDMATRIX_X4(fa[nxt][0], fa[nxt][1], fa[nxt][2], fa[nxt][3], sa + a_lm_off[ks + 1]);
                LDMATRIX_X4(fb[nxt][0][0], fb[nxt][0][1], fb[nxt][1][0], fb[nxt][1][1], sb + b4_off[0][ks + 1]);
                LDMATRIX_X4(fb[nxt][2][0], fb[nxt][2][1], fb[nxt][3][0], fb[nxt][3][1], sb + b4_off[1][ks + 1]);
                LDMATRIX_X2(fb[nxt][4][0], fb[nxt][4][1], sb + b2_off[ks + 1]);
            }
            #pragma unroll
            for (int nf = 0; nf < 5; nf++)
                MMA_16816(acc[nf][0], acc[nf][1], acc[nf][2], acc[nf][3],
                          fa[cur][0], fa[cur][1], fa[cur][2], fa[cur][3],
                          fb[cur][nf][0], fb[cur][nf][1]);
        }
    }
    __syncthreads();   // all reads done before epilogue overwrites stage 0/1

    // ---- fused epilogue: fragments -> SMEM stage -> per-(row,class) logsumexp ----
    float* sst = reinterpret_cast<float*>(smem);            // [64][44]
    float* st3 = reinterpret_cast<float*>(smem + T3_OFF);   // [40]
    if (tid < 40) st3[tid] = g_t3[n0 + tid];

    const int qr = lid >> 2;
    const int qc = (lid & 3) * 2;
    {
        int row = wm + qr;
        #pragma unroll
        for (int nf = 0; nf < 5; nf++) {
            int col = nf * 8 + qc;
            *reinterpret_cast<float2*>(&sst[row * SST_STRIDE + col]) =
                make_float2(acc[nf][0], acc[nf][1]);
            *reinterpret_cast<float2*>(&sst[(row + 8) * SST_STRIDE + col]) =
                make_float2(acc[nf][2], acc[nf][3]);
        }
    }
    __syncthreads();

    // 64 rows x 4 classes = 256 tasks, 2 per thread
    const int c0 = blockIdx.x * 4;
    #pragma unroll
    for (int i = 0; i < 2; i++) {
        int task = tid + i * NTHREADS;
        int row = task >> 2;
        int cls = task & 3;
        const float* sp = &sst[row * SST_STRIDE + cls * 10];
        const float* tp = &st3[cls * 10];
        float v[10], mx = -3.4e38f;
        #pragma unroll
        for (int p = 0; p < 10; p++) {
            v[p] = -(sp[p] + tp[p]);
            mx = fmaxf(mx, v[p]);
        }
        float s = 0.f;
        #pragma unroll
        for (int p = 0; p < 10; p++) s += expf(v[p] - mx);
        float t1v = flag ? 0.f : g_t1[m0 + row];   // fast path: t1 slid out of lse
        out[(size_t)(m0 + row) * 100 + c0 + cls] = mx + logf(s) - t1v;
    }
}

// ---------------- launch ----------------
extern "C" void kernel_launch(void* const* d_in, const int* in_sizes, int n_in,
                              void* d_out, int out_size) {
    const float* x     = (const float*)d_in[0];  // (1024, 512)
    const float* proto = (const float*)d_in[1];  // (100, 10, 512)
    const float* ls    = (const float*)d_in[2];  // (100, 10, 512)
    float* out = (float*)d_out;                  // (1024, 100)

    cudaFuncSetAttribute(gemm_lse_kernel, cudaFuncAttributeMaxDynamicSharedMemorySize, SMEM_TOTAL);

    prep_kernel<<<756, 256>>>(x, proto, ls);     // x+t1 (256 blocks) | proto+t3+flag (500)
    gemm_lse_kernel<<<dim3(25, MB / BM), NTHREADS, SMEM_TOTAL>>>(out);
}